// round 7
// baseline (speedup 1.0000x reference)
#include <cuda_runtime.h>
#include <cstdint>
#include <float.h>

#define FIN  128
#define FOUT 64
#define NEG  0.2f
#define NMAX 50048
#define EMAX 1000192

// ---------------- scratch (device globals; no allocations allowed) ----------
__device__ float    g_Wh[NMAX * FOUT];
__device__ float    g_ssrc[NMAX];
__device__ float    g_sdst[NMAX];
__device__ int      g_deg[NMAX];
__device__ int      g_cursor[NMAX];
__device__ int      g_rowstart[NMAX + 1];
__device__ uint2    g_bkt[EMAX];        // (src, bitcast(e)) bucketed by dst
__device__ unsigned g_maxflip;
__device__ int      g_is64;

// ---------------- edge-index accessor (dtype decided at runtime) ------------
__device__ __forceinline__ void load_edge(const void* ei, int is64, int E,
                                          int i, int N, int& s, int& d) {
    if (is64) {
        const long long* p = (const long long*)ei;
        s = (int)p[i];
        d = (int)p[E + i];
    } else {
        const int* p = (const int*)ei;
        s = p[i];
        d = p[E + i];
    }
    s = min(max(s, 0), N - 1);
    d = min(max(d, 0), N - 1);
}

// ---------------- 0a) detect int64 vs int32 edge index ----------------------
// Reads only the first min(2E, 65536) uint32 words — in-bounds for BOTH dtypes.
// int64 data: odd words are hi-words of values < 50000 -> all zero.
__global__ void detect_kernel(const unsigned* __restrict__ w, int nwords,
                              int* __restrict__ is64) {
    __shared__ unsigned sh[32];
    unsigned acc = 0;
    for (int i = threadIdx.x * 2 + 1; i < nwords; i += blockDim.x * 2)
        acc |= w[i];
#pragma unroll
    for (int o = 16; o; o >>= 1) acc |= __shfl_xor_sync(0xFFFFFFFFu, acc, o);
    if ((threadIdx.x & 31) == 0) sh[threadIdx.x >> 5] = acc;
    __syncthreads();
    if (threadIdx.x < 32) {
        unsigned v = (threadIdx.x < (blockDim.x >> 5)) ? sh[threadIdx.x] : 0u;
#pragma unroll
        for (int o = 16; o; o >>= 1) v |= __shfl_xor_sync(0xFFFFFFFFu, v, o);
        if (threadIdx.x == 0) *is64 = (v == 0u) ? 1 : 0;
    }
}

// ---------------- 0b) init ---------------------------------------------------
__global__ void init_kernel(int* __restrict__ deg, int* __restrict__ cursor,
                            unsigned* __restrict__ maxflip, int N) {
    int i = blockIdx.x * blockDim.x + threadIdx.x;
    if (i < N) { deg[i] = 0; cursor[i] = 0; }
    if (i == 0) *maxflip = 0u;
}

// ---------------- 1) GEMM: Wh = x @ W  (M=N, K=128, N=64) ------------------
__global__ void gemm_kernel(const float* __restrict__ x,
                            const float* __restrict__ W,
                            float* __restrict__ Wh, int N) {
    extern __shared__ float sm[];
    float* xs = sm;              // 128*128
    float* ws = sm + 128 * 128;  // 128*64

    int tid = threadIdx.x;

    const float4* W4 = (const float4*)W;
    float4* ws4 = (float4*)ws;
#pragma unroll
    for (int i = 0; i < 8; i++) ws4[tid + i * 256] = W4[tid + i * 256];

    int r0 = blockIdx.x * 128;
    const float4* x4 = (const float4*)x;
    float4* xs4 = (float4*)xs;
#pragma unroll
    for (int i = 0; i < 16; i++) {
        int idx = tid + i * 256;
        int row = idx >> 5;
        int g = r0 + row;
        float4 v = make_float4(0.f, 0.f, 0.f, 0.f);
        if (g < N) v = x4[(size_t)g * 32 + (idx & 31)];
        xs4[idx] = v;
    }
    __syncthreads();

    int colBase = (tid & 15) * 4;
    int rowBase = (tid >> 4) * 8;

    float acc[8][4];
#pragma unroll
    for (int i = 0; i < 8; i++)
#pragma unroll
        for (int j = 0; j < 4; j++) acc[i][j] = 0.f;

#pragma unroll 4
    for (int k4 = 0; k4 < 32; k4++) {
        float4 w0 = *(float4*)&ws[(k4 * 4 + 0) * 64 + colBase];
        float4 w1 = *(float4*)&ws[(k4 * 4 + 1) * 64 + colBase];
        float4 w2 = *(float4*)&ws[(k4 * 4 + 2) * 64 + colBase];
        float4 w3 = *(float4*)&ws[(k4 * 4 + 3) * 64 + colBase];
#pragma unroll
        for (int i = 0; i < 8; i++) {
            float4 xv = *(float4*)&xs[(rowBase + i) * 128 + k4 * 4];
            acc[i][0] += xv.x * w0.x + xv.y * w1.x + xv.z * w2.x + xv.w * w3.x;
            acc[i][1] += xv.x * w0.y + xv.y * w1.y + xv.z * w2.y + xv.w * w3.y;
            acc[i][2] += xv.x * w0.z + xv.y * w1.z + xv.z * w2.z + xv.w * w3.z;
            acc[i][3] += xv.x * w0.w + xv.y * w1.w + xv.z * w2.w + xv.w * w3.w;
        }
    }

#pragma unroll
    for (int i = 0; i < 8; i++) {
        int g = r0 + rowBase + i;
        if (g < N)
            *(float4*)&Wh[(size_t)g * FOUT + colBase] =
                make_float4(acc[i][0], acc[i][1], acc[i][2], acc[i][3]);
    }
}

// ---------------- 2) per-node scores: s = Wh . a ----------------------------
__global__ void s_kernel(const float* __restrict__ Wh,
                         const float* __restrict__ a_src,
                         const float* __restrict__ a_dst,
                         float* __restrict__ ssrc, float* __restrict__ sdst,
                         int N) {
    int t = blockIdx.x * blockDim.x + threadIdx.x;
    int row = t >> 5;
    int lane = t & 31;
    if (row >= N) return;
    float2 w  = *(const float2*)&Wh[(size_t)row * FOUT + lane * 2];
    float2 as = *(const float2*)&a_src[lane * 2];
    float2 ad = *(const float2*)&a_dst[lane * 2];
    float ps = w.x * as.x + w.y * as.y;
    float pd = w.x * ad.x + w.y * ad.y;
#pragma unroll
    for (int o = 16; o; o >>= 1) {
        ps += __shfl_xor_sync(0xFFFFFFFFu, ps, o);
        pd += __shfl_xor_sync(0xFFFFFFFFu, pd, o);
    }
    if (lane == 0) { ssrc[row] = ps; sdst[row] = pd; }
}

// ---------------- float<->orderable-uint for atomicMax ----------------------
__device__ __forceinline__ unsigned flip_f(float f) {
    unsigned u = __float_as_uint(f);
    return u ^ ((u >> 31) ? 0xFFFFFFFFu : 0x80000000u);
}
__device__ __forceinline__ float unflip_f(unsigned u) {
    u ^= ((u >> 31) ? 0x80000000u : 0xFFFFFFFFu);
    return __uint_as_float(u);
}

// ---------------- 3) degree count + global max of raw logits ----------------
__global__ void countmax_kernel(const void* __restrict__ ei,
                                const int* __restrict__ is64p,
                                const float* __restrict__ ssrc,
                                const float* __restrict__ sdst,
                                int* __restrict__ deg,
                                unsigned* __restrict__ maxflip, int E, int N) {
    int is64 = *is64p;
    float m = -FLT_MAX;
    for (int i = blockIdx.x * blockDim.x + threadIdx.x; i < E;
         i += gridDim.x * blockDim.x) {
        int s, d;
        load_edge(ei, is64, E, i, N, s, d);
        atomicAdd(&deg[d], 1);
        m = fmaxf(m, ssrc[s] + sdst[d]);
    }
#pragma unroll
    for (int o = 16; o; o >>= 1) m = fmaxf(m, __shfl_xor_sync(0xFFFFFFFFu, m, o));
    __shared__ float smx[8];
    if ((threadIdx.x & 31) == 0) smx[threadIdx.x >> 5] = m;
    __syncthreads();
    if (threadIdx.x < 8) {
        m = smx[threadIdx.x];
#pragma unroll
        for (int o = 4; o; o >>= 1) m = fmaxf(m, __shfl_xor_sync(0xFFu, m, o));
        if (threadIdx.x == 0) atomicMax(maxflip, flip_f(m));
    }
}

// ---------------- 4) exclusive prefix scan of degrees (single block) --------
__global__ void scan_kernel(const int* __restrict__ deg,
                            int* __restrict__ rowstart, int N) {
    __shared__ int sh[1024];
    int t = threadIdx.x;
    int chunk = (N + 1023) >> 10;
    int base = t * chunk;
    int local = 0;
    for (int i = 0; i < chunk; i++) {
        int idx = base + i;
        if (idx < N) local += deg[idx];
    }
    sh[t] = local;
    __syncthreads();
    for (int off = 1; off < 1024; off <<= 1) {
        int v = (t >= off) ? sh[t - off] : 0;
        __syncthreads();
        sh[t] += v;
        __syncthreads();
    }
    int run = (t == 0) ? 0 : sh[t - 1];
    for (int i = 0; i < chunk; i++) {
        int idx = base + i;
        if (idx < N) { rowstart[idx] = run; run += deg[idx]; }
    }
    if (t == 0) rowstart[N] = sh[1023];
}

// ---------------- 5) bucket edges by dst: store (src, e) --------------------
__global__ void fill_kernel(const void* __restrict__ ei,
                            const int* __restrict__ is64p,
                            const float* __restrict__ ssrc,
                            const float* __restrict__ sdst,
                            const unsigned* __restrict__ maxflip,
                            const int* __restrict__ rowstart,
                            int* __restrict__ cursor,
                            uint2* __restrict__ bkt, int E, int N) {
    int i = blockIdx.x * blockDim.x + threadIdx.x;
    if (i >= E) return;
    int is64 = *is64p;
    int s, d;
    load_edge(ei, is64, E, i, N, s, d);
    float t = ssrc[s] + sdst[d];
    float l = t > 0.f ? t : NEG * t;
    float mt = unflip_f(*maxflip);
    float M = mt > 0.f ? mt : NEG * mt;
    float e = __expf(l - M);
    int pos = atomicAdd(&cursor[d], 1);
    bkt[rowstart[d] + pos] = make_uint2((unsigned)s, __float_as_uint(e));
}

// ---------------- 6) gather: out[n] = elu( (Σ e·Wh[src]) / Σe ) -------------
// One warp per node; lane owns 2 output columns (float2).
__global__ void gather_kernel(const uint2* __restrict__ bkt,
                              const int* __restrict__ rowstart,
                              const float* __restrict__ Wh,
                              float* __restrict__ out, int N) {
    int warp = (blockIdx.x * blockDim.x + threadIdx.x) >> 5;
    int lane = threadIdx.x & 31;
    if (warp >= N) return;
    int beg = rowstart[warp];
    int end = rowstart[warp + 1];
    float ax = 0.f, ay = 0.f, denom = 0.f;
    for (int j = beg; j < end; j++) {
        uint2 b = __ldg(&bkt[j]);
        float e = __uint_as_float(b.y);
        denom += e;
        float2 w = *(const float2*)&Wh[(size_t)b.x * FOUT + lane * 2];
        ax = fmaf(e, w.x, ax);
        ay = fmaf(e, w.y, ay);
    }
    float inv = __fdividef(1.f, denom + 1e-16f);
    float vx = ax * inv, vy = ay * inv;
    vx = vx > 0.f ? vx : expm1f(vx);
    vy = vy > 0.f ? vy : expm1f(vy);
    *(float2*)&out[(size_t)warp * FOUT + lane * 2] = make_float2(vx, vy);
}

// ---------------- launch ----------------------------------------------------
extern "C" void kernel_launch(void* const* d_in, const int* in_sizes, int n_in,
                              void* d_out, int out_size) {
    // Bind inputs by element count, not by position.
    const float* x = 0;
    const void*  ei = 0;
    const float* W = 0;
    const float* a_src = 0;
    const float* a_dst = 0;
    int x_sz = 0, ei_sz = 0;

    for (int i = 0; i < n_in; i++) {
        int sz = in_sizes[i];
        if (sz == 64) {
            if (!a_src) a_src = (const float*)d_in[i];
            else        a_dst = (const float*)d_in[i];
        } else if (sz == FIN * FOUT) {
            W = (const float*)d_in[i];
        } else if (sz > x_sz) {
            // largest remaining = x, second = edge_index (resolved below)
            if (x) { if (x_sz < ei_sz || !ei) {} }
            // shift current x down to ei if new one is bigger
            ei = (const void*)x; ei_sz = x_sz;
            x = (const float*)d_in[i]; x_sz = sz;
        } else {
            ei = (const void*)d_in[i]; ei_sz = sz;
        }
    }

    float* out = (float*)d_out;
    int N = x_sz / FIN;
    int E = ei_sz / 2;

    void *pWh, *pss, *psd, *pdeg, *pcur, *prow, *pbkt, *pmax, *p64;
    cudaGetSymbolAddress(&pWh, g_Wh);
    cudaGetSymbolAddress(&pss, g_ssrc);
    cudaGetSymbolAddress(&psd, g_sdst);
    cudaGetSymbolAddress(&pdeg, g_deg);
    cudaGetSymbolAddress(&pcur, g_cursor);
    cudaGetSymbolAddress(&prow, g_rowstart);
    cudaGetSymbolAddress(&pbkt, g_bkt);
    cudaGetSymbolAddress(&pmax, g_maxflip);
    cudaGetSymbolAddress(&p64, g_is64);

    int nwords = 2 * E < 65536 ? 2 * E : 65536;
    detect_kernel<<<1, 1024>>>((const unsigned*)ei, nwords, (int*)p64);

    init_kernel<<<(N + 255) / 256, 256>>>((int*)pdeg, (int*)pcur,
                                          (unsigned*)pmax, N);

    cudaFuncSetAttribute(gemm_kernel,
                         cudaFuncAttributeMaxDynamicSharedMemorySize, 96 * 1024);
    gemm_kernel<<<(N + 127) / 128, 256, 96 * 1024>>>(x, W, (float*)pWh, N);

    s_kernel<<<(N * 32 + 255) / 256, 256>>>((float*)pWh, a_src, a_dst,
                                            (float*)pss, (float*)psd, N);

    countmax_kernel<<<(E + 255) / 256, 256>>>(ei, (int*)p64, (float*)pss,
                                              (float*)psd, (int*)pdeg,
                                              (unsigned*)pmax, E, N);

    scan_kernel<<<1, 1024>>>((int*)pdeg, (int*)prow, N);

    fill_kernel<<<(E + 255) / 256, 256>>>(ei, (int*)p64, (float*)pss,
                                          (float*)psd, (unsigned*)pmax,
                                          (int*)prow, (int*)pcur,
                                          (uint2*)pbkt, E, N);

    long long gthreads = (long long)N * 32;
    gather_kernel<<<(int)((gthreads + 255) / 256), 256>>>(
        (uint2*)pbkt, (int*)prow, (float*)pWh, out, N);
}

// round 9
// speedup vs baseline: 1.6771x; 1.6771x over previous
#include <cuda_runtime.h>
#include <cstdint>
#include <float.h>

#define FIN  128
#define FOUT 64
#define NEG  0.2f
#define NMAX 50048
#define EMAX 1000192

// ---------------- scratch (device globals; no allocations allowed) ----------
__device__ float    g_Wh[NMAX * FOUT];
__device__ float    g_ssrc[NMAX];
__device__ float    g_sdst[NMAX];
__device__ int      g_deg[NMAX];
__device__ int      g_cursor[NMAX];
__device__ int      g_rowstart[NMAX + 1];
__device__ uint2    g_bkt[EMAX];        // (src, bitcast(e)) bucketed by dst
__device__ unsigned g_maxflip;
__device__ int      g_is64;

// ---------------- edge-index accessor (dtype decided at runtime) ------------
__device__ __forceinline__ void load_edge(const void* ei, int is64, int E,
                                          int i, int N, int& s, int& d) {
    if (is64) {
        const long long* p = (const long long*)ei;
        s = (int)p[i];
        d = (int)p[E + i];
    } else {
        const int* p = (const int*)ei;
        s = p[i];
        d = p[E + i];
    }
    s = min(max(s, 0), N - 1);
    d = min(max(d, 0), N - 1);
}

// ---------------- 0) init + dtype detect (block 0) ---------------------------
// Detect: scan first 1024 uint32 words (in-bounds for both dtypes since
// 2E elements >= 1024 either way). int64 data: odd words are hi-words of
// small nonneg values -> all zero. int32: 512 random indices, P(all 0) ~ 0.
__global__ void init_kernel(const unsigned* __restrict__ eiw,
                            int* __restrict__ deg, int* __restrict__ cursor,
                            unsigned* __restrict__ maxflip,
                            int* __restrict__ is64, int N) {
    int i = blockIdx.x * blockDim.x + threadIdx.x;
    if (i < N) { deg[i] = 0; cursor[i] = 0; }
    if (i == 0) *maxflip = 0u;

    if (blockIdx.x == 0) {
        __shared__ unsigned sh[8];
        unsigned acc = 0;
        for (int w = threadIdx.x * 2 + 1; w < 1024; w += blockDim.x * 2)
            acc |= eiw[w];
#pragma unroll
        for (int o = 16; o; o >>= 1)
            acc |= __shfl_xor_sync(0xFFFFFFFFu, acc, o);
        if ((threadIdx.x & 31) == 0) sh[threadIdx.x >> 5] = acc;
        __syncthreads();
        if (threadIdx.x < 8) {
            unsigned v = sh[threadIdx.x];
#pragma unroll
            for (int o = 4; o; o >>= 1)
                v |= __shfl_xor_sync(0xFFu, v, o);
            if (threadIdx.x == 0) *is64 = (v == 0u) ? 1 : 0;
        }
    }
}

// ---------------- 1) GEMM: Wh = x @ W, fused s = Wh.a epilogue --------------
// Block tile 128x64, 256 threads, thread tile 8x4, 96KB smem.
__global__ void gemm_kernel(const float* __restrict__ x,
                            const float* __restrict__ W,
                            const float* __restrict__ a_src,
                            const float* __restrict__ a_dst,
                            float* __restrict__ Wh,
                            float* __restrict__ ssrc,
                            float* __restrict__ sdst, int N) {
    extern __shared__ float sm[];
    float* xs = sm;              // 128*128
    float* ws = sm + 128 * 128;  // 128*64

    int tid = threadIdx.x;

    const float4* W4 = (const float4*)W;
    float4* ws4 = (float4*)ws;
#pragma unroll
    for (int i = 0; i < 8; i++) ws4[tid + i * 256] = W4[tid + i * 256];

    int r0 = blockIdx.x * 128;
    const float4* x4 = (const float4*)x;
    float4* xs4 = (float4*)xs;
#pragma unroll
    for (int i = 0; i < 16; i++) {
        int idx = tid + i * 256;
        int row = idx >> 5;
        int g = r0 + row;
        float4 v = make_float4(0.f, 0.f, 0.f, 0.f);
        if (g < N) v = x4[(size_t)g * 32 + (idx & 31)];
        xs4[idx] = v;
    }
    __syncthreads();

    int t16 = tid & 15;
    int colBase = t16 * 4;
    int rowBase = (tid >> 4) * 8;

    float acc[8][4];
#pragma unroll
    for (int i = 0; i < 8; i++)
#pragma unroll
        for (int j = 0; j < 4; j++) acc[i][j] = 0.f;

#pragma unroll 4
    for (int k4 = 0; k4 < 32; k4++) {
        float4 w0 = *(float4*)&ws[(k4 * 4 + 0) * 64 + colBase];
        float4 w1 = *(float4*)&ws[(k4 * 4 + 1) * 64 + colBase];
        float4 w2 = *(float4*)&ws[(k4 * 4 + 2) * 64 + colBase];
        float4 w3 = *(float4*)&ws[(k4 * 4 + 3) * 64 + colBase];
#pragma unroll
        for (int i = 0; i < 8; i++) {
            float4 xv = *(float4*)&xs[(rowBase + i) * 128 + k4 * 4];
            acc[i][0] += xv.x * w0.x + xv.y * w1.x + xv.z * w2.x + xv.w * w3.x;
            acc[i][1] += xv.x * w0.y + xv.y * w1.y + xv.z * w2.y + xv.w * w3.y;
            acc[i][2] += xv.x * w0.z + xv.y * w1.z + xv.z * w2.z + xv.w * w3.z;
            acc[i][3] += xv.x * w0.w + xv.y * w1.w + xv.z * w2.w + xv.w * w3.w;
        }
    }

#pragma unroll
    for (int i = 0; i < 8; i++) {
        int g = r0 + rowBase + i;
        if (g < N)
            *(float4*)&Wh[(size_t)g * FOUT + colBase] =
                make_float4(acc[i][0], acc[i][1], acc[i][2], acc[i][3]);
    }

    // ---- fused s epilogue: partial dots into (reused) smem, then reduce ----
    float4 asv = *(const float4*)&a_src[colBase];
    float4 adv = *(const float4*)&a_dst[colBase];

    __syncthreads();               // done with xs/ws reads
    float* ps = sm;                // 128*17
    float* pd = sm + 128 * 17;     // 128*17
#pragma unroll
    for (int i = 0; i < 8; i++) {
        int row = rowBase + i;
        float vs = acc[i][0] * asv.x + acc[i][1] * asv.y +
                   acc[i][2] * asv.z + acc[i][3] * asv.w;
        float vd = acc[i][0] * adv.x + acc[i][1] * adv.y +
                   acc[i][2] * adv.z + acc[i][3] * adv.w;
        ps[row * 17 + t16] = vs;
        pd[row * 17 + t16] = vd;
    }
    __syncthreads();
    if (tid < 128) {
        float s1 = 0.f, s2 = 0.f;
#pragma unroll
        for (int k = 0; k < 16; k++) {
            s1 += ps[tid * 17 + k];
            s2 += pd[tid * 17 + k];
        }
        int g = r0 + tid;
        if (g < N) { ssrc[g] = s1; sdst[g] = s2; }
    }
}

// ---------------- float<->orderable-uint for atomicMax ----------------------
__device__ __forceinline__ unsigned flip_f(float f) {
    unsigned u = __float_as_uint(f);
    return u ^ ((u >> 31) ? 0xFFFFFFFFu : 0x80000000u);
}
__device__ __forceinline__ float unflip_f(unsigned u) {
    u ^= ((u >> 31) ? 0x80000000u : 0xFFFFFFFFu);
    return __uint_as_float(u);
}

// ---------------- 2) degree count + global max of raw logits ----------------
__global__ void countmax_kernel(const void* __restrict__ ei,
                                const int* __restrict__ is64p,
                                const float* __restrict__ ssrc,
                                const float* __restrict__ sdst,
                                int* __restrict__ deg,
                                unsigned* __restrict__ maxflip, int E, int N) {
    int is64 = *is64p;
    float m = -FLT_MAX;
    for (int i = blockIdx.x * blockDim.x + threadIdx.x; i < E;
         i += gridDim.x * blockDim.x) {
        int s, d;
        load_edge(ei, is64, E, i, N, s, d);
        atomicAdd(&deg[d], 1);
        m = fmaxf(m, ssrc[s] + sdst[d]);
    }
#pragma unroll
    for (int o = 16; o; o >>= 1) m = fmaxf(m, __shfl_xor_sync(0xFFFFFFFFu, m, o));
    __shared__ float smx[8];
    if ((threadIdx.x & 31) == 0) smx[threadIdx.x >> 5] = m;
    __syncthreads();
    if (threadIdx.x < 8) {
        m = smx[threadIdx.x];
#pragma unroll
        for (int o = 4; o; o >>= 1) m = fmaxf(m, __shfl_xor_sync(0xFFu, m, o));
        if (threadIdx.x == 0) atomicMax(maxflip, flip_f(m));
    }
}

// ---------------- 3) exclusive prefix scan of degrees (single block) --------
__global__ void scan_kernel(const int* __restrict__ deg,
                            int* __restrict__ rowstart, int N) {
    __shared__ int sh[1024];
    int t = threadIdx.x;
    int chunk = (N + 1023) >> 10;
    int base = t * chunk;
    int local = 0;
    for (int i = 0; i < chunk; i++) {
        int idx = base + i;
        if (idx < N) local += deg[idx];
    }
    sh[t] = local;
    __syncthreads();
    for (int off = 1; off < 1024; off <<= 1) {
        int v = (t >= off) ? sh[t - off] : 0;
        __syncthreads();
        sh[t] += v;
        __syncthreads();
    }
    int run = (t == 0) ? 0 : sh[t - 1];
    for (int i = 0; i < chunk; i++) {
        int idx = base + i;
        if (idx < N) { rowstart[idx] = run; run += deg[idx]; }
    }
    if (t == 0) rowstart[N] = sh[1023];
}

// ---------------- 4) bucket edges by dst: store (src, e) --------------------
__global__ void fill_kernel(const void* __restrict__ ei,
                            const int* __restrict__ is64p,
                            const float* __restrict__ ssrc,
                            const float* __restrict__ sdst,
                            const unsigned* __restrict__ maxflip,
                            const int* __restrict__ rowstart,
                            int* __restrict__ cursor,
                            uint2* __restrict__ bkt, int E, int N) {
    int i = blockIdx.x * blockDim.x + threadIdx.x;
    if (i >= E) return;
    int is64 = *is64p;
    int s, d;
    load_edge(ei, is64, E, i, N, s, d);
    float t = ssrc[s] + sdst[d];
    float l = t > 0.f ? t : NEG * t;
    float mt = unflip_f(*maxflip);
    float M = mt > 0.f ? mt : NEG * mt;
    float e = __expf(l - M);
    int pos = atomicAdd(&cursor[d], 1);
    bkt[rowstart[d] + pos] = make_uint2((unsigned)s, __float_as_uint(e));
}

// ---------------- 5) gather: out[n] = elu( (Σ e·Wh[src]) / Σe ) -------------
// 16 threads per node (2 nodes/warp); lane owns 4 output cols (float4).
// 2-way unrolled: dual load streams for MLP.
__global__ void gather_kernel(const uint2* __restrict__ bkt,
                              const int* __restrict__ rowstart,
                              const float* __restrict__ Wh,
                              float* __restrict__ out, int N) {
    int t = blockIdx.x * blockDim.x + threadIdx.x;
    int node = t >> 4;
    int l = t & 15;
    if (node >= N) return;
    int beg = rowstart[node];
    int end = rowstart[node + 1];

    float4 a0 = make_float4(0.f, 0.f, 0.f, 0.f);
    float4 a1 = make_float4(0.f, 0.f, 0.f, 0.f);
    float den0 = 0.f, den1 = 0.f;

    int j = beg;
    for (; j + 2 <= end; j += 2) {
        uint2 b0 = __ldg(&bkt[j]);
        uint2 b1 = __ldg(&bkt[j + 1]);
        float4 w0 = *(const float4*)&Wh[(size_t)b0.x * FOUT + l * 4];
        float4 w1 = *(const float4*)&Wh[(size_t)b1.x * FOUT + l * 4];
        float e0 = __uint_as_float(b0.y);
        float e1 = __uint_as_float(b1.y);
        den0 += e0;
        den1 += e1;
        a0.x = fmaf(e0, w0.x, a0.x); a0.y = fmaf(e0, w0.y, a0.y);
        a0.z = fmaf(e0, w0.z, a0.z); a0.w = fmaf(e0, w0.w, a0.w);
        a1.x = fmaf(e1, w1.x, a1.x); a1.y = fmaf(e1, w1.y, a1.y);
        a1.z = fmaf(e1, w1.z, a1.z); a1.w = fmaf(e1, w1.w, a1.w);
    }
    if (j < end) {
        uint2 b0 = __ldg(&bkt[j]);
        float4 w0 = *(const float4*)&Wh[(size_t)b0.x * FOUT + l * 4];
        float e0 = __uint_as_float(b0.y);
        den0 += e0;
        a0.x = fmaf(e0, w0.x, a0.x); a0.y = fmaf(e0, w0.y, a0.y);
        a0.z = fmaf(e0, w0.z, a0.z); a0.w = fmaf(e0, w0.w, a0.w);
    }

    float denom = den0 + den1;
    a0.x += a1.x; a0.y += a1.y; a0.z += a1.z; a0.w += a1.w;

    float inv = __fdividef(1.f, denom + 1e-16f);
    a0.x *= inv; a0.y *= inv; a0.z *= inv; a0.w *= inv;
    a0.x = a0.x > 0.f ? a0.x : expm1f(a0.x);
    a0.y = a0.y > 0.f ? a0.y : expm1f(a0.y);
    a0.z = a0.z > 0.f ? a0.z : expm1f(a0.z);
    a0.w = a0.w > 0.f ? a0.w : expm1f(a0.w);
    *(float4*)&out[(size_t)node * FOUT + l * 4] = a0;
}

// ---------------- launch ----------------------------------------------------
extern "C" void kernel_launch(void* const* d_in, const int* in_sizes, int n_in,
                              void* d_out, int out_size) {
    // Bind inputs by element count, not by position.
    const float* x = 0;
    const void*  ei = 0;
    const float* W = 0;
    const float* a_src = 0;
    const float* a_dst = 0;
    int x_sz = 0, ei_sz = 0;

    for (int i = 0; i < n_in; i++) {
        int sz = in_sizes[i];
        if (sz == 64) {
            if (!a_src) a_src = (const float*)d_in[i];
            else        a_dst = (const float*)d_in[i];
        } else if (sz == FIN * FOUT) {
            W = (const float*)d_in[i];
        } else if (sz > x_sz) {
            ei = (const void*)x; ei_sz = x_sz;
            x = (const float*)d_in[i]; x_sz = sz;
        } else {
            ei = (const void*)d_in[i]; ei_sz = sz;
        }
    }

    float* out = (float*)d_out;
    int N = x_sz / FIN;
    int E = ei_sz / 2;

    void *pWh, *pss, *psd, *pdeg, *pcur, *prow, *pbkt, *pmax, *p64;
    cudaGetSymbolAddress(&pWh, g_Wh);
    cudaGetSymbolAddress(&pss, g_ssrc);
    cudaGetSymbolAddress(&psd, g_sdst);
    cudaGetSymbolAddress(&pdeg, g_deg);
    cudaGetSymbolAddress(&pcur, g_cursor);
    cudaGetSymbolAddress(&prow, g_rowstart);
    cudaGetSymbolAddress(&pbkt, g_bkt);
    cudaGetSymbolAddress(&pmax, g_maxflip);
    cudaGetSymbolAddress(&p64, g_is64);

    init_kernel<<<(N + 255) / 256, 256>>>((const unsigned*)ei, (int*)pdeg,
                                          (int*)pcur, (unsigned*)pmax,
                                          (int*)p64, N);

    cudaFuncSetAttribute(gemm_kernel,
                         cudaFuncAttributeMaxDynamicSharedMemorySize, 96 * 1024);
    gemm_kernel<<<(N + 127) / 128, 256, 96 * 1024>>>(
        x, W, a_src, a_dst, (float*)pWh, (float*)pss, (float*)psd, N);

    countmax_kernel<<<(E + 255) / 256, 256>>>(ei, (int*)p64, (float*)pss,
                                              (float*)psd, (int*)pdeg,
                                              (unsigned*)pmax, E, N);

    scan_kernel<<<1, 1024>>>((int*)pdeg, (int*)prow, N);

    fill_kernel<<<(E + 255) / 256, 256>>>(ei, (int*)p64, (float*)pss,
                                          (float*)psd, (unsigned*)pmax,
                                          (int*)prow, (int*)pcur,
                                          (uint2*)pbkt, E, N);

    long long gthreads = (long long)N * 16;
    gather_kernel<<<(int)((gthreads + 255) / 256), 256>>>(
        (uint2*)pbkt, (int*)prow, (float*)pWh, out, N);
}

// round 11
// speedup vs baseline: 2.5226x; 1.5042x over previous
#include <cuda_runtime.h>
#include <cstdint>
#include <float.h>

#define FIN  128
#define FOUT 64
#define NEG  0.2f
#define NMAX 50048
#define EMAX 1000192

// ---------------- scratch (device globals; no allocations allowed) ----------
__device__ float    g_Wh[NMAX * FOUT];
__device__ float    g_ssrc[NMAX];
__device__ float    g_sdst[NMAX];
__device__ int      g_deg[NMAX];
__device__ int      g_cursor[NMAX];
__device__ int      g_rowstart[NMAX + 1];
__device__ uint2    g_bkt[EMAX];        // (src, bitcast(e)) bucketed by dst
__device__ unsigned g_maxflip;
__device__ int      g_is64;
__device__ int      g_total;            // bump allocator for bucket space

// ---------------- edge-index accessor (dtype decided at runtime) ------------
__device__ __forceinline__ void load_edge(const void* ei, int is64, int E,
                                          int i, int N, int& s, int& d) {
    if (is64) {
        const long long* p = (const long long*)ei;
        s = (int)p[i];
        d = (int)p[E + i];
    } else {
        const int* p = (const int*)ei;
        s = p[i];
        d = p[E + i];
    }
    s = min(max(s, 0), N - 1);
    d = min(max(d, 0), N - 1);
}

// ---------------- 0) init + dtype detect (block 0) ---------------------------
__global__ void init_kernel(const unsigned* __restrict__ eiw,
                            int* __restrict__ deg, int* __restrict__ cursor,
                            unsigned* __restrict__ maxflip,
                            int* __restrict__ is64, int* __restrict__ total,
                            int N) {
    int i = blockIdx.x * blockDim.x + threadIdx.x;
    if (i < N) { deg[i] = 0; cursor[i] = 0; }
    if (i == 0) { *maxflip = 0u; *total = 0; }

    if (blockIdx.x == 0) {
        __shared__ unsigned sh[8];
        unsigned acc = 0;
        for (int w = threadIdx.x * 2 + 1; w < 1024; w += blockDim.x * 2)
            acc |= eiw[w];
#pragma unroll
        for (int o = 16; o; o >>= 1)
            acc |= __shfl_xor_sync(0xFFFFFFFFu, acc, o);
        if ((threadIdx.x & 31) == 0) sh[threadIdx.x >> 5] = acc;
        __syncthreads();
        if (threadIdx.x < 8) {
            unsigned v = sh[threadIdx.x];
#pragma unroll
            for (int o = 4; o; o >>= 1)
                v |= __shfl_xor_sync(0xFFu, v, o);
            if (threadIdx.x == 0) *is64 = (v == 0u) ? 1 : 0;
        }
    }
}

// ---------------- 1) GEMM: Wh = x @ W, fused s = Wh.a epilogue --------------
__global__ void gemm_kernel(const float* __restrict__ x,
                            const float* __restrict__ W,
                            const float* __restrict__ a_src,
                            const float* __restrict__ a_dst,
                            float* __restrict__ Wh,
                            float* __restrict__ ssrc,
                            float* __restrict__ sdst, int N) {
    extern __shared__ float sm[];
    float* xs = sm;              // 128*128
    float* ws = sm + 128 * 128;  // 128*64

    int tid = threadIdx.x;

    const float4* W4 = (const float4*)W;
    float4* ws4 = (float4*)ws;
#pragma unroll
    for (int i = 0; i < 8; i++) ws4[tid + i * 256] = W4[tid + i * 256];

    int r0 = blockIdx.x * 128;
    const float4* x4 = (const float4*)x;
    float4* xs4 = (float4*)xs;
#pragma unroll
    for (int i = 0; i < 16; i++) {
        int idx = tid + i * 256;
        int row = idx >> 5;
        int g = r0 + row;
        float4 v = make_float4(0.f, 0.f, 0.f, 0.f);
        if (g < N) v = x4[(size_t)g * 32 + (idx & 31)];
        xs4[idx] = v;
    }
    __syncthreads();

    int t16 = tid & 15;
    int colBase = t16 * 4;
    int rowBase = (tid >> 4) * 8;

    float acc[8][4];
#pragma unroll
    for (int i = 0; i < 8; i++)
#pragma unroll
        for (int j = 0; j < 4; j++) acc[i][j] = 0.f;

#pragma unroll 4
    for (int k4 = 0; k4 < 32; k4++) {
        float4 w0 = *(float4*)&ws[(k4 * 4 + 0) * 64 + colBase];
        float4 w1 = *(float4*)&ws[(k4 * 4 + 1) * 64 + colBase];
        float4 w2 = *(float4*)&ws[(k4 * 4 + 2) * 64 + colBase];
        float4 w3 = *(float4*)&ws[(k4 * 4 + 3) * 64 + colBase];
#pragma unroll
        for (int i = 0; i < 8; i++) {
            float4 xv = *(float4*)&xs[(rowBase + i) * 128 + k4 * 4];
            acc[i][0] += xv.x * w0.x + xv.y * w1.x + xv.z * w2.x + xv.w * w3.x;
            acc[i][1] += xv.x * w0.y + xv.y * w1.y + xv.z * w2.y + xv.w * w3.y;
            acc[i][2] += xv.x * w0.z + xv.y * w1.z + xv.z * w2.z + xv.w * w3.z;
            acc[i][3] += xv.x * w0.w + xv.y * w1.w + xv.z * w2.w + xv.w * w3.w;
        }
    }

#pragma unroll
    for (int i = 0; i < 8; i++) {
        int g = r0 + rowBase + i;
        if (g < N)
            *(float4*)&Wh[(size_t)g * FOUT + colBase] =
                make_float4(acc[i][0], acc[i][1], acc[i][2], acc[i][3]);
    }

    // ---- fused s epilogue ----
    float4 asv = *(const float4*)&a_src[colBase];
    float4 adv = *(const float4*)&a_dst[colBase];

    __syncthreads();
    float* ps = sm;                // 128*17
    float* pd = sm + 128 * 17;     // 128*17
#pragma unroll
    for (int i = 0; i < 8; i++) {
        int row = rowBase + i;
        float vs = acc[i][0] * asv.x + acc[i][1] * asv.y +
                   acc[i][2] * asv.z + acc[i][3] * asv.w;
        float vd = acc[i][0] * adv.x + acc[i][1] * adv.y +
                   acc[i][2] * adv.z + acc[i][3] * adv.w;
        ps[row * 17 + t16] = vs;
        pd[row * 17 + t16] = vd;
    }
    __syncthreads();
    if (tid < 128) {
        float s1 = 0.f, s2 = 0.f;
#pragma unroll
        for (int k = 0; k < 16; k++) {
            s1 += ps[tid * 17 + k];
            s2 += pd[tid * 17 + k];
        }
        int g = r0 + tid;
        if (g < N) { ssrc[g] = s1; sdst[g] = s2; }
    }
}

// ---------------- float<->orderable-uint for atomicMax ----------------------
__device__ __forceinline__ unsigned flip_f(float f) {
    unsigned u = __float_as_uint(f);
    return u ^ ((u >> 31) ? 0xFFFFFFFFu : 0x80000000u);
}
__device__ __forceinline__ float unflip_f(unsigned u) {
    u ^= ((u >> 31) ? 0x80000000u : 0xFFFFFFFFu);
    return __uint_as_float(u);
}

// ---------------- 2) degree count + global max of raw logits ----------------
__global__ void countmax_kernel(const void* __restrict__ ei,
                                const int* __restrict__ is64p,
                                const float* __restrict__ ssrc,
                                const float* __restrict__ sdst,
                                int* __restrict__ deg,
                                unsigned* __restrict__ maxflip, int E, int N) {
    int is64 = *is64p;
    float m = -FLT_MAX;
    for (int i = blockIdx.x * blockDim.x + threadIdx.x; i < E;
         i += gridDim.x * blockDim.x) {
        int s, d;
        load_edge(ei, is64, E, i, N, s, d);
        atomicAdd(&deg[d], 1);
        m = fmaxf(m, ssrc[s] + sdst[d]);
    }
#pragma unroll
    for (int o = 16; o; o >>= 1) m = fmaxf(m, __shfl_xor_sync(0xFFFFFFFFu, m, o));
    __shared__ float smx[8];
    if ((threadIdx.x & 31) == 0) smx[threadIdx.x >> 5] = m;
    __syncthreads();
    if (threadIdx.x < 8) {
        m = smx[threadIdx.x];
#pragma unroll
        for (int o = 4; o; o >>= 1) m = fmaxf(m, __shfl_xor_sync(0xFFu, m, o));
        if (threadIdx.x == 0) atomicMax(maxflip, flip_f(m));
    }
}

// ---------------- 3) unordered bucket allocation (replaces prefix scan) -----
// Gather only needs each node's bucket contiguous, NOT node-ordered buckets.
// Block-local exclusive scan + one bump-pointer atomic per block.
__global__ void alloc_kernel(const int* __restrict__ deg,
                             int* __restrict__ rowstart,
                             int* __restrict__ total, int N) {
    __shared__ int warpsum[8];
    __shared__ int blockbase;
    int i = blockIdx.x * blockDim.x + threadIdx.x;
    int lane = threadIdx.x & 31;
    int wid = threadIdx.x >> 5;

    int v = (i < N) ? deg[i] : 0;
    // warp inclusive scan
    int sc = v;
#pragma unroll
    for (int o = 1; o < 32; o <<= 1) {
        int t = __shfl_up_sync(0xFFFFFFFFu, sc, o);
        if (lane >= o) sc += t;
    }
    if (lane == 31) warpsum[wid] = sc;
    __syncthreads();
    if (threadIdx.x < 8) {
        int ws = warpsum[threadIdx.x];
        int s2 = ws;
#pragma unroll
        for (int o = 1; o < 8; o <<= 1) {
            int t = __shfl_up_sync(0xFFu, s2, o);
            if ((int)threadIdx.x >= o) s2 += t;
        }
        warpsum[threadIdx.x] = s2 - ws;  // exclusive warp base
        if (threadIdx.x == 7) blockbase = atomicAdd(total, s2);
    }
    __syncthreads();
    if (i < N) rowstart[i] = blockbase + warpsum[wid] + (sc - v);
}

// ---------------- 4) bucket edges by dst: store (src, e) --------------------
__global__ void fill_kernel(const void* __restrict__ ei,
                            const int* __restrict__ is64p,
                            const float* __restrict__ ssrc,
                            const float* __restrict__ sdst,
                            const unsigned* __restrict__ maxflip,
                            const int* __restrict__ rowstart,
                            int* __restrict__ cursor,
                            uint2* __restrict__ bkt, int E, int N) {
    int i = blockIdx.x * blockDim.x + threadIdx.x;
    if (i >= E) return;
    int is64 = *is64p;
    int s, d;
    load_edge(ei, is64, E, i, N, s, d);
    float t = ssrc[s] + sdst[d];
    float l = t > 0.f ? t : NEG * t;
    float mt = unflip_f(*maxflip);
    float M = mt > 0.f ? mt : NEG * mt;
    float e = __expf(l - M);
    int pos = atomicAdd(&cursor[d], 1);
    bkt[rowstart[d] + pos] = make_uint2((unsigned)s, __float_as_uint(e));
}

// ---------------- 5) gather: out[n] = elu( (Σ e·Wh[src]) / Σe ) -------------
// 16 threads per node; lane owns 4 output cols (float4); 2-way unroll.
__global__ void gather_kernel(const uint2* __restrict__ bkt,
                              const int* __restrict__ rowstart,
                              const int* __restrict__ deg,
                              const float* __restrict__ Wh,
                              float* __restrict__ out, int N) {
    int t = blockIdx.x * blockDim.x + threadIdx.x;
    int node = t >> 4;
    int l = t & 15;
    if (node >= N) return;
    int beg = rowstart[node];
    int end = beg + deg[node];

    float4 a0 = make_float4(0.f, 0.f, 0.f, 0.f);
    float4 a1 = make_float4(0.f, 0.f, 0.f, 0.f);
    float den0 = 0.f, den1 = 0.f;

    int j = beg;
    for (; j + 2 <= end; j += 2) {
        uint2 b0 = __ldg(&bkt[j]);
        uint2 b1 = __ldg(&bkt[j + 1]);
        float4 w0 = *(const float4*)&Wh[(size_t)b0.x * FOUT + l * 4];
        float4 w1 = *(const float4*)&Wh[(size_t)b1.x * FOUT + l * 4];
        float e0 = __uint_as_float(b0.y);
        float e1 = __uint_as_float(b1.y);
        den0 += e0;
        den1 += e1;
        a0.x = fmaf(e0, w0.x, a0.x); a0.y = fmaf(e0, w0.y, a0.y);
        a0.z = fmaf(e0, w0.z, a0.z); a0.w = fmaf(e0, w0.w, a0.w);
        a1.x = fmaf(e1, w1.x, a1.x); a1.y = fmaf(e1, w1.y, a1.y);
        a1.z = fmaf(e1, w1.z, a1.z); a1.w = fmaf(e1, w1.w, a1.w);
    }
    if (j < end) {
        uint2 b0 = __ldg(&bkt[j]);
        float4 w0 = *(const float4*)&Wh[(size_t)b0.x * FOUT + l * 4];
        float e0 = __uint_as_float(b0.y);
        den0 += e0;
        a0.x = fmaf(e0, w0.x, a0.x); a0.y = fmaf(e0, w0.y, a0.y);
        a0.z = fmaf(e0, w0.z, a0.z); a0.w = fmaf(e0, w0.w, a0.w);
    }

    float denom = den0 + den1;
    a0.x += a1.x; a0.y += a1.y; a0.z += a1.z; a0.w += a1.w;

    float inv = __fdividef(1.f, denom + 1e-16f);
    a0.x *= inv; a0.y *= inv; a0.z *= inv; a0.w *= inv;
    a0.x = a0.x > 0.f ? a0.x : expm1f(a0.x);
    a0.y = a0.y > 0.f ? a0.y : expm1f(a0.y);
    a0.z = a0.z > 0.f ? a0.z : expm1f(a0.z);
    a0.w = a0.w > 0.f ? a0.w : expm1f(a0.w);
    *(float4*)&out[(size_t)node * FOUT + l * 4] = a0;
}

// ---------------- launch ----------------------------------------------------
extern "C" void kernel_launch(void* const* d_in, const int* in_sizes, int n_in,
                              void* d_out, int out_size) {
    const float* x = 0;
    const void*  ei = 0;
    const float* W = 0;
    const float* a_src = 0;
    const float* a_dst = 0;
    int x_sz = 0, ei_sz = 0;

    for (int i = 0; i < n_in; i++) {
        int sz = in_sizes[i];
        if (sz == 64) {
            if (!a_src) a_src = (const float*)d_in[i];
            else        a_dst = (const float*)d_in[i];
        } else if (sz == FIN * FOUT) {
            W = (const float*)d_in[i];
        } else if (sz > x_sz) {
            ei = (const void*)x; ei_sz = x_sz;
            x = (const float*)d_in[i]; x_sz = sz;
        } else {
            ei = (const void*)d_in[i]; ei_sz = sz;
        }
    }

    float* out = (float*)d_out;
    int N = x_sz / FIN;
    int E = ei_sz / 2;

    void *pWh, *pss, *psd, *pdeg, *pcur, *prow, *pbkt, *pmax, *p64, *ptot;
    cudaGetSymbolAddress(&pWh, g_Wh);
    cudaGetSymbolAddress(&pss, g_ssrc);
    cudaGetSymbolAddress(&psd, g_sdst);
    cudaGetSymbolAddress(&pdeg, g_deg);
    cudaGetSymbolAddress(&pcur, g_cursor);
    cudaGetSymbolAddress(&prow, g_rowstart);
    cudaGetSymbolAddress(&pbkt, g_bkt);
    cudaGetSymbolAddress(&pmax, g_maxflip);
    cudaGetSymbolAddress(&p64, g_is64);
    cudaGetSymbolAddress(&ptot, g_total);

    init_kernel<<<(N + 255) / 256, 256>>>((const unsigned*)ei, (int*)pdeg,
                                          (int*)pcur, (unsigned*)pmax,
                                          (int*)p64, (int*)ptot, N);

    cudaFuncSetAttribute(gemm_kernel,
                         cudaFuncAttributeMaxDynamicSharedMemorySize, 96 * 1024);
    gemm_kernel<<<(N + 127) / 128, 256, 96 * 1024>>>(
        x, W, a_src, a_dst, (float*)pWh, (float*)pss, (float*)psd, N);

    countmax_kernel<<<(E + 255) / 256, 256>>>(ei, (int*)p64, (float*)pss,
                                              (float*)psd, (int*)pdeg,
                                              (unsigned*)pmax, E, N);

    alloc_kernel<<<(N + 255) / 256, 256>>>((int*)pdeg, (int*)prow,
                                           (int*)ptot, N);

    fill_kernel<<<(E + 255) / 256, 256>>>(ei, (int*)p64, (float*)pss,
                                          (float*)psd, (unsigned*)pmax,
                                          (int*)prow, (int*)pcur,
                                          (uint2*)pbkt, E, N);

    long long gthreads = (long long)N * 16;
    gather_kernel<<<(int)((gthreads + 255) / 256), 256>>>(
        (uint2*)pbkt, (int*)prow, (int*)pdeg, (float*)pWh, out, N);
}

// round 12
// speedup vs baseline: 2.5823x; 1.0237x over previous
#include <cuda_runtime.h>
#include <cuda_fp16.h>
#include <cstdint>
#include <float.h>

#define FIN  128
#define FOUT 64
#define NEG  0.2f
#define NMAX 50048
#define EMAX 1000192

// ---------------- scratch (device globals; no allocations allowed) ----------
__device__ __half   g_Whh[NMAX * FOUT];   // fp16 Wh (gather-only consumer)
__device__ float    g_ssrc[NMAX];
__device__ float    g_sdst[NMAX];
__device__ int      g_deg[NMAX];
__device__ int      g_cursor[NMAX];
__device__ int      g_rowstart[NMAX + 1];
__device__ uint2    g_bkt[EMAX];          // (src, bitcast(e)) bucketed by dst
__device__ unsigned g_maxflip;
__device__ int      g_is64;
__device__ int      g_total;              // bump allocator for bucket space

// ---------------- edge-index accessor (dtype decided at runtime) ------------
__device__ __forceinline__ void load_edge(const void* ei, int is64, int E,
                                          int i, int N, int& s, int& d) {
    if (is64) {
        const long long* p = (const long long*)ei;
        s = (int)p[i];
        d = (int)p[E + i];
    } else {
        const int* p = (const int*)ei;
        s = p[i];
        d = p[E + i];
    }
    s = min(max(s, 0), N - 1);
    d = min(max(d, 0), N - 1);
}

// ---------------- 0) init + dtype detect (block 0) ---------------------------
__global__ void init_kernel(const unsigned* __restrict__ eiw,
                            int* __restrict__ deg, int* __restrict__ cursor,
                            unsigned* __restrict__ maxflip,
                            int* __restrict__ is64, int* __restrict__ total,
                            int N) {
    int i = blockIdx.x * blockDim.x + threadIdx.x;
    if (i < N) { deg[i] = 0; cursor[i] = 0; }
    if (i == 0) { *maxflip = 0u; *total = 0; }

    if (blockIdx.x == 0) {
        __shared__ unsigned sh[8];
        unsigned acc = 0;
        for (int w = threadIdx.x * 2 + 1; w < 1024; w += blockDim.x * 2)
            acc |= eiw[w];
#pragma unroll
        for (int o = 16; o; o >>= 1)
            acc |= __shfl_xor_sync(0xFFFFFFFFu, acc, o);
        if ((threadIdx.x & 31) == 0) sh[threadIdx.x >> 5] = acc;
        __syncthreads();
        if (threadIdx.x < 8) {
            unsigned v = sh[threadIdx.x];
#pragma unroll
            for (int o = 4; o; o >>= 1)
                v |= __shfl_xor_sync(0xFFu, v, o);
            if (threadIdx.x == 0) *is64 = (v == 0u) ? 1 : 0;
        }
    }
}

// ---------------- 1) GEMM: Wh = x @ W (fp16 store), fused s epilogue --------
__global__ void gemm_kernel(const float* __restrict__ x,
                            const float* __restrict__ W,
                            const float* __restrict__ a_src,
                            const float* __restrict__ a_dst,
                            __half* __restrict__ Whh,
                            float* __restrict__ ssrc,
                            float* __restrict__ sdst, int N) {
    extern __shared__ float sm[];
    float* xs = sm;              // 128*128
    float* ws = sm + 128 * 128;  // 128*64

    int tid = threadIdx.x;

    const float4* W4 = (const float4*)W;
    float4* ws4 = (float4*)ws;
#pragma unroll
    for (int i = 0; i < 8; i++) ws4[tid + i * 256] = W4[tid + i * 256];

    int r0 = blockIdx.x * 128;
    const float4* x4 = (const float4*)x;
    float4* xs4 = (float4*)xs;
#pragma unroll
    for (int i = 0; i < 16; i++) {
        int idx = tid + i * 256;
        int row = idx >> 5;
        int g = r0 + row;
        float4 v = make_float4(0.f, 0.f, 0.f, 0.f);
        if (g < N) v = x4[(size_t)g * 32 + (idx & 31)];
        xs4[idx] = v;
    }
    __syncthreads();

    int t16 = tid & 15;
    int colBase = t16 * 4;
    int rowBase = (tid >> 4) * 8;

    float acc[8][4];
#pragma unroll
    for (int i = 0; i < 8; i++)
#pragma unroll
        for (int j = 0; j < 4; j++) acc[i][j] = 0.f;

#pragma unroll 4
    for (int k4 = 0; k4 < 32; k4++) {
        float4 w0 = *(float4*)&ws[(k4 * 4 + 0) * 64 + colBase];
        float4 w1 = *(float4*)&ws[(k4 * 4 + 1) * 64 + colBase];
        float4 w2 = *(float4*)&ws[(k4 * 4 + 2) * 64 + colBase];
        float4 w3 = *(float4*)&ws[(k4 * 4 + 3) * 64 + colBase];
#pragma unroll
        for (int i = 0; i < 8; i++) {
            float4 xv = *(float4*)&xs[(rowBase + i) * 128 + k4 * 4];
            acc[i][0] += xv.x * w0.x + xv.y * w1.x + xv.z * w2.x + xv.w * w3.x;
            acc[i][1] += xv.x * w0.y + xv.y * w1.y + xv.z * w2.y + xv.w * w3.y;
            acc[i][2] += xv.x * w0.z + xv.y * w1.z + xv.z * w2.z + xv.w * w3.z;
            acc[i][3] += xv.x * w0.w + xv.y * w1.w + xv.z * w2.w + xv.w * w3.w;
        }
    }

    // fp16 store of Wh (8B per thread-row: two half2)
#pragma unroll
    for (int i = 0; i < 8; i++) {
        int g = r0 + rowBase + i;
        if (g < N) {
            __half2 h0 = __float22half2_rn(make_float2(acc[i][0], acc[i][1]));
            __half2 h1 = __float22half2_rn(make_float2(acc[i][2], acc[i][3]));
            uint2 pk = make_uint2(*(unsigned*)&h0, *(unsigned*)&h1);
            *(uint2*)&Whh[(size_t)g * FOUT + colBase] = pk;
        }
    }

    // ---- fused s epilogue (fp32 accumulators) ----
    float4 asv = *(const float4*)&a_src[colBase];
    float4 adv = *(const float4*)&a_dst[colBase];

    __syncthreads();
    float* ps = sm;                // 128*17
    float* pd = sm + 128 * 17;     // 128*17
#pragma unroll
    for (int i = 0; i < 8; i++) {
        int row = rowBase + i;
        float vs = acc[i][0] * asv.x + acc[i][1] * asv.y +
                   acc[i][2] * asv.z + acc[i][3] * asv.w;
        float vd = acc[i][0] * adv.x + acc[i][1] * adv.y +
                   acc[i][2] * adv.z + acc[i][3] * adv.w;
        ps[row * 17 + t16] = vs;
        pd[row * 17 + t16] = vd;
    }
    __syncthreads();
    if (tid < 128) {
        float s1 = 0.f, s2 = 0.f;
#pragma unroll
        for (int k = 0; k < 16; k++) {
            s1 += ps[tid * 17 + k];
            s2 += pd[tid * 17 + k];
        }
        int g = r0 + tid;
        if (g < N) { ssrc[g] = s1; sdst[g] = s2; }
    }
}

// ---------------- float<->orderable-uint for atomicMax ----------------------
__device__ __forceinline__ unsigned flip_f(float f) {
    unsigned u = __float_as_uint(f);
    return u ^ ((u >> 31) ? 0xFFFFFFFFu : 0x80000000u);
}
__device__ __forceinline__ float unflip_f(unsigned u) {
    u ^= ((u >> 31) ? 0x80000000u : 0xFFFFFFFFu);
    return __uint_as_float(u);
}

// ---------------- 2) degree count + global max of raw logits ----------------
__global__ void countmax_kernel(const void* __restrict__ ei,
                                const int* __restrict__ is64p,
                                const float* __restrict__ ssrc,
                                const float* __restrict__ sdst,
                                int* __restrict__ deg,
                                unsigned* __restrict__ maxflip, int E, int N) {
    int is64 = *is64p;
    float m = -FLT_MAX;
    for (int i = blockIdx.x * blockDim.x + threadIdx.x; i < E;
         i += gridDim.x * blockDim.x) {
        int s, d;
        load_edge(ei, is64, E, i, N, s, d);
        atomicAdd(&deg[d], 1);
        m = fmaxf(m, ssrc[s] + sdst[d]);
    }
#pragma unroll
    for (int o = 16; o; o >>= 1) m = fmaxf(m, __shfl_xor_sync(0xFFFFFFFFu, m, o));
    __shared__ float smx[8];
    if ((threadIdx.x & 31) == 0) smx[threadIdx.x >> 5] = m;
    __syncthreads();
    if (threadIdx.x < 8) {
        m = smx[threadIdx.x];
#pragma unroll
        for (int o = 4; o; o >>= 1) m = fmaxf(m, __shfl_xor_sync(0xFFu, m, o));
        if (threadIdx.x == 0) atomicMax(maxflip, flip_f(m));
    }
}

// ---------------- 3) unordered bucket allocation ----------------------------
__global__ void alloc_kernel(const int* __restrict__ deg,
                             int* __restrict__ rowstart,
                             int* __restrict__ total, int N) {
    __shared__ int warpsum[8];
    __shared__ int blockbase;
    int i = blockIdx.x * blockDim.x + threadIdx.x;
    int lane = threadIdx.x & 31;
    int wid = threadIdx.x >> 5;

    int v = (i < N) ? deg[i] : 0;
    int sc = v;
#pragma unroll
    for (int o = 1; o < 32; o <<= 1) {
        int t = __shfl_up_sync(0xFFFFFFFFu, sc, o);
        if (lane >= o) sc += t;
    }
    if (lane == 31) warpsum[wid] = sc;
    __syncthreads();
    if (threadIdx.x < 8) {
        int ws = warpsum[threadIdx.x];
        int s2 = ws;
#pragma unroll
        for (int o = 1; o < 8; o <<= 1) {
            int t = __shfl_up_sync(0xFFu, s2, o);
            if ((int)threadIdx.x >= o) s2 += t;
        }
        warpsum[threadIdx.x] = s2 - ws;
        if (threadIdx.x == 7) blockbase = atomicAdd(total, s2);
    }
    __syncthreads();
    if (i < N) rowstart[i] = blockbase + warpsum[wid] + (sc - v);
}

// ---------------- 4) bucket edges by dst: store (src, e) --------------------
__global__ void fill_kernel(const void* __restrict__ ei,
                            const int* __restrict__ is64p,
                            const float* __restrict__ ssrc,
                            const float* __restrict__ sdst,
                            const unsigned* __restrict__ maxflip,
                            const int* __restrict__ rowstart,
                            int* __restrict__ cursor,
                            uint2* __restrict__ bkt, int E, int N) {
    int i = blockIdx.x * blockDim.x + threadIdx.x;
    if (i >= E) return;
    int is64 = *is64p;
    int s, d;
    load_edge(ei, is64, E, i, N, s, d);
    float t = ssrc[s] + sdst[d];
    float l = t > 0.f ? t : NEG * t;
    float mt = unflip_f(*maxflip);
    float M = mt > 0.f ? mt : NEG * mt;
    float e = __expf(l - M);
    int pos = atomicAdd(&cursor[d], 1);
    bkt[rowstart[d] + pos] = make_uint2((unsigned)s, __float_as_uint(e));
}

// ---------------- 5) gather: out[n] = elu( (Σ e·Wh[src]) / Σe ) -------------
// 8 threads per node; lane owns 8 cols (one 16B uint4 of 8 halves); 2-way
// unroll for MLP. Accumulation in fp32.
__global__ void gather_kernel(const uint2* __restrict__ bkt,
                              const int* __restrict__ rowstart,
                              const int* __restrict__ deg,
                              const __half* __restrict__ Whh,
                              float* __restrict__ out, int N) {
    int t = blockIdx.x * blockDim.x + threadIdx.x;
    int node = t >> 3;
    int l = t & 7;
    if (node >= N) return;
    int beg = rowstart[node];
    int end = beg + deg[node];

    float a0[8], a1[8];
#pragma unroll
    for (int k = 0; k < 8; k++) { a0[k] = 0.f; a1[k] = 0.f; }
    float den0 = 0.f, den1 = 0.f;

    int j = beg;
    for (; j + 2 <= end; j += 2) {
        uint2 b0 = __ldg(&bkt[j]);
        uint2 b1 = __ldg(&bkt[j + 1]);
        uint4 v0 = *(const uint4*)&Whh[(size_t)b0.x * FOUT + l * 8];
        uint4 v1 = *(const uint4*)&Whh[(size_t)b1.x * FOUT + l * 8];
        float e0 = __uint_as_float(b0.y);
        float e1 = __uint_as_float(b1.y);
        den0 += e0;
        den1 += e1;
        {
            float2 f0 = __half22float2(*(__half2*)&v0.x);
            float2 f1 = __half22float2(*(__half2*)&v0.y);
            float2 f2 = __half22float2(*(__half2*)&v0.z);
            float2 f3 = __half22float2(*(__half2*)&v0.w);
            a0[0] = fmaf(e0, f0.x, a0[0]); a0[1] = fmaf(e0, f0.y, a0[1]);
            a0[2] = fmaf(e0, f1.x, a0[2]); a0[3] = fmaf(e0, f1.y, a0[3]);
            a0[4] = fmaf(e0, f2.x, a0[4]); a0[5] = fmaf(e0, f2.y, a0[5]);
            a0[6] = fmaf(e0, f3.x, a0[6]); a0[7] = fmaf(e0, f3.y, a0[7]);
        }
        {
            float2 f0 = __half22float2(*(__half2*)&v1.x);
            float2 f1 = __half22float2(*(__half2*)&v1.y);
            float2 f2 = __half22float2(*(__half2*)&v1.z);
            float2 f3 = __half22float2(*(__half2*)&v1.w);
            a1[0] = fmaf(e1, f0.x, a1[0]); a1[1] = fmaf(e1, f0.y, a1[1]);
            a1[2] = fmaf(e1, f1.x, a1[2]); a1[3] = fmaf(e1, f1.y, a1[3]);
            a1[4] = fmaf(e1, f2.x, a1[4]); a1[5] = fmaf(e1, f2.y, a1[5]);
            a1[6] = fmaf(e1, f3.x, a1[6]); a1[7] = fmaf(e1, f3.y, a1[7]);
        }
    }
    if (j < end) {
        uint2 b0 = __ldg(&bkt[j]);
        uint4 v0 = *(const uint4*)&Whh[(size_t)b0.x * FOUT + l * 8];
        float e0 = __uint_as_float(b0.y);
        den0 += e0;
        float2 f0 = __half22float2(*(__half2*)&v0.x);
        float2 f1 = __half22float2(*(__half2*)&v0.y);
        float2 f2 = __half22float2(*(__half2*)&v0.z);
        float2 f3 = __half22float2(*(__half2*)&v0.w);
        a0[0] = fmaf(e0, f0.x, a0[0]); a0[1] = fmaf(e0, f0.y, a0[1]);
        a0[2] = fmaf(e0, f1.x, a0[2]); a0[3] = fmaf(e0, f1.y, a0[3]);
        a0[4] = fmaf(e0, f2.x, a0[4]); a0[5] = fmaf(e0, f2.y, a0[5]);
        a0[6] = fmaf(e0, f3.x, a0[6]); a0[7] = fmaf(e0, f3.y, a0[7]);
    }

    float denom = den0 + den1;
    float inv = __fdividef(1.f, denom + 1e-16f);

    float4 o0, o1;
    float r[8];
#pragma unroll
    for (int k = 0; k < 8; k++) {
        float v = (a0[k] + a1[k]) * inv;
        r[k] = v > 0.f ? v : expm1f(v);
    }
    o0 = make_float4(r[0], r[1], r[2], r[3]);
    o1 = make_float4(r[4], r[5], r[6], r[7]);
    *(float4*)&out[(size_t)node * FOUT + l * 8] = o0;
    *(float4*)&out[(size_t)node * FOUT + l * 8 + 4] = o1;
}

// ---------------- launch ----------------------------------------------------
extern "C" void kernel_launch(void* const* d_in, const int* in_sizes, int n_in,
                              void* d_out, int out_size) {
    const float* x = 0;
    const void*  ei = 0;
    const float* W = 0;
    const float* a_src = 0;
    const float* a_dst = 0;
    int x_sz = 0, ei_sz = 0;

    for (int i = 0; i < n_in; i++) {
        int sz = in_sizes[i];
        if (sz == 64) {
            if (!a_src) a_src = (const float*)d_in[i];
            else        a_dst = (const float*)d_in[i];
        } else if (sz == FIN * FOUT) {
            W = (const float*)d_in[i];
        } else if (sz > x_sz) {
            ei = (const void*)x; ei_sz = x_sz;
            x = (const float*)d_in[i]; x_sz = sz;
        } else {
            ei = (const void*)d_in[i]; ei_sz = sz;
        }
    }

    float* out = (float*)d_out;
    int N = x_sz / FIN;
    int E = ei_sz / 2;

    void *pWhh, *pss, *psd, *pdeg, *pcur, *prow, *pbkt, *pmax, *p64, *ptot;
    cudaGetSymbolAddress(&pWhh, g_Whh);
    cudaGetSymbolAddress(&pss, g_ssrc);
    cudaGetSymbolAddress(&psd, g_sdst);
    cudaGetSymbolAddress(&pdeg, g_deg);
    cudaGetSymbolAddress(&pcur, g_cursor);
    cudaGetSymbolAddress(&prow, g_rowstart);
    cudaGetSymbolAddress(&pbkt, g_bkt);
    cudaGetSymbolAddress(&pmax, g_maxflip);
    cudaGetSymbolAddress(&p64, g_is64);
    cudaGetSymbolAddress(&ptot, g_total);

    init_kernel<<<(N + 255) / 256, 256>>>((const unsigned*)ei, (int*)pdeg,
                                          (int*)pcur, (unsigned*)pmax,
                                          (int*)p64, (int*)ptot, N);

    cudaFuncSetAttribute(gemm_kernel,
                         cudaFuncAttributeMaxDynamicSharedMemorySize, 96 * 1024);
    gemm_kernel<<<(N + 127) / 128, 256, 96 * 1024>>>(
        x, W, a_src, a_dst, (__half*)pWhh, (float*)pss, (float*)psd, N);

    countmax_kernel<<<(E + 255) / 256, 256>>>(ei, (int*)p64, (float*)pss,
                                              (float*)psd, (int*)pdeg,
                                              (unsigned*)pmax, E, N);

    alloc_kernel<<<(N + 255) / 256, 256>>>((int*)pdeg, (int*)prow,
                                           (int*)ptot, N);

    fill_kernel<<<(E + 255) / 256, 256>>>(ei, (int*)p64, (float*)pss,
                                          (float*)psd, (unsigned*)pmax,
                                          (int*)prow, (int*)pcur,
                                          (uint2*)pbkt, E, N);

    long long gthreads = (long long)N * 8;
    gather_kernel<<<(int)((gthreads + 255) / 256), 256>>>(
        (uint2*)pbkt, (int*)prow, (int*)pdeg, (const __half*)pWhh, out, N);
}

// round 13
// speedup vs baseline: 2.9279x; 1.1338x over previous
#include <cuda_runtime.h>
#include <cuda_fp16.h>
#include <cstdint>
#include <float.h>

#define FIN  128
#define FOUT 64
#define NEG  0.2f
#define NMAX 50048
#define EMAX 1000192

// ---------------- scratch (device globals; zero-initialized at load) --------
// Invariant: deg[], cursor[] are zero at kernel_launch entry; restored by
// gather's epilogue each run. g_total is zeroed by count each run.
__device__ __half   g_Whh[NMAX * FOUT];   // fp16 Wh (gather-only consumer)
__device__ float    g_ssrc[NMAX];
__device__ float    g_sdst[NMAX];
__device__ int      g_deg[NMAX];
__device__ int      g_cursor[NMAX];
__device__ int      g_rowstart[NMAX];
__device__ uint2    g_bkt[EMAX];          // (src, bitcast(e)) bucketed by dst
__device__ int      g_total;              // bump allocator for bucket space

// ---------------- per-block edge-dtype detect --------------------------------
// Reads first 128 uint32 words (in-bounds both dtypes). int64 data: odd words
// are hi-words of small nonneg values -> all zero. int32: 64 random indices,
// P(all zero) ~ (1/50000)^64 ~ 0.
__device__ __forceinline__ int detect_is64(const unsigned* eiw) {
    unsigned v = 0;
    if (threadIdx.x < 64) v = eiw[threadIdx.x * 2 + 1];
    return __syncthreads_or(v != 0u) ? 0 : 1;
}

__device__ __forceinline__ void load_edge(const void* ei, int is64, int E,
                                          int i, int N, int& s, int& d) {
    if (is64) {
        const long long* p = (const long long*)ei;
        s = (int)p[i];
        d = (int)p[E + i];
    } else {
        const int* p = (const int*)ei;
        s = p[i];
        d = p[E + i];
    }
    s = min(max(s, 0), N - 1);
    d = min(max(d, 0), N - 1);
}

// ---------------- 1) count: deg[dst]++ (dst stream only) --------------------
__global__ void count_kernel(const void* __restrict__ ei,
                             int* __restrict__ deg, int* __restrict__ total,
                             int E, int N) {
    int is64 = detect_is64((const unsigned*)ei);
    if (blockIdx.x == 0 && threadIdx.x == 0) *total = 0;
    for (int i = blockIdx.x * blockDim.x + threadIdx.x; i < E;
         i += gridDim.x * blockDim.x) {
        int d;
        if (is64) d = (int)((const long long*)ei)[E + i];
        else      d = ((const int*)ei)[E + i];
        d = min(max(d, 0), N - 1);
        atomicAdd(&deg[d], 1);
    }
}

// ---------------- 2) GEMM + s epilogue + alloc tail blocks ------------------
__global__ void gemm_kernel(const float* __restrict__ x,
                            const float* __restrict__ W,
                            const float* __restrict__ a_src,
                            const float* __restrict__ a_dst,
                            __half* __restrict__ Whh,
                            float* __restrict__ ssrc,
                            float* __restrict__ sdst,
                            const int* __restrict__ deg,
                            int* __restrict__ rowstart,
                            int* __restrict__ total,
                            int gemmBlocks, int N) {
    extern __shared__ float sm[];
    int tid = threadIdx.x;

    // ======== alloc path (tail blocks): unordered bucket allocation ========
    // Gather only needs per-node-contiguous buckets, not node-ordered ones:
    // block-local exclusive scan of deg + one bump atomic per block.
    if (blockIdx.x >= gemmBlocks) {
        int* warpsum = (int*)sm;          // 8 ints
        int* blockbase = (int*)sm + 8;    // 1 int
        int i = (blockIdx.x - gemmBlocks) * blockDim.x + tid;
        int lane = tid & 31;
        int wid = tid >> 5;

        int v = (i < N) ? deg[i] : 0;
        int sc = v;
#pragma unroll
        for (int o = 1; o < 32; o <<= 1) {
            int t = __shfl_up_sync(0xFFFFFFFFu, sc, o);
            if (lane >= o) sc += t;
        }
        if (lane == 31) warpsum[wid] = sc;
        __syncthreads();
        if (tid < 8) {
            int ws = warpsum[tid];
            int s2 = ws;
#pragma unroll
            for (int o = 1; o < 8; o <<= 1) {
                int t = __shfl_up_sync(0xFFu, s2, o);
                if (tid >= o) s2 += t;
            }
            warpsum[tid] = s2 - ws;
            if (tid == 7) *blockbase = atomicAdd(total, s2);
        }
        __syncthreads();
        if (i < N) rowstart[i] = *blockbase + warpsum[wid] + (sc - v);
        return;
    }

    // ======== GEMM path ========
    float* xs = sm;              // 128*128
    float* ws = sm + 128 * 128;  // 128*64

    const float4* W4 = (const float4*)W;
    float4* ws4 = (float4*)ws;
#pragma unroll
    for (int i = 0; i < 8; i++) ws4[tid + i * 256] = W4[tid + i * 256];

    int r0 = blockIdx.x * 128;
    const float4* x4 = (const float4*)x;
    float4* xs4 = (float4*)xs;
#pragma unroll
    for (int i = 0; i < 16; i++) {
        int idx = tid + i * 256;
        int row = idx >> 5;
        int g = r0 + row;
        float4 v = make_float4(0.f, 0.f, 0.f, 0.f);
        if (g < N) v = x4[(size_t)g * 32 + (idx & 31)];
        xs4[idx] = v;
    }
    __syncthreads();

    int t16 = tid & 15;
    int colBase = t16 * 4;
    int rowBase = (tid >> 4) * 8;

    float acc[8][4];
#pragma unroll
    for (int i = 0; i < 8; i++)
#pragma unroll
        for (int j = 0; j < 4; j++) acc[i][j] = 0.f;

#pragma unroll 4
    for (int k4 = 0; k4 < 32; k4++) {
        float4 w0 = *(float4*)&ws[(k4 * 4 + 0) * 64 + colBase];
        float4 w1 = *(float4*)&ws[(k4 * 4 + 1) * 64 + colBase];
        float4 w2 = *(float4*)&ws[(k4 * 4 + 2) * 64 + colBase];
        float4 w3 = *(float4*)&ws[(k4 * 4 + 3) * 64 + colBase];
#pragma unroll
        for (int i = 0; i < 8; i++) {
            float4 xv = *(float4*)&xs[(rowBase + i) * 128 + k4 * 4];
            acc[i][0] += xv.x * w0.x + xv.y * w1.x + xv.z * w2.x + xv.w * w3.x;
            acc[i][1] += xv.x * w0.y + xv.y * w1.y + xv.z * w2.y + xv.w * w3.y;
            acc[i][2] += xv.x * w0.z + xv.y * w1.z + xv.z * w2.z + xv.w * w3.z;
            acc[i][3] += xv.x * w0.w + xv.y * w1.w + xv.z * w2.w + xv.w * w3.w;
        }
    }

    // fp16 store of Wh
#pragma unroll
    for (int i = 0; i < 8; i++) {
        int g = r0 + rowBase + i;
        if (g < N) {
            __half2 h0 = __float22half2_rn(make_float2(acc[i][0], acc[i][1]));
            __half2 h1 = __float22half2_rn(make_float2(acc[i][2], acc[i][3]));
            uint2 pk = make_uint2(*(unsigned*)&h0, *(unsigned*)&h1);
            *(uint2*)&Whh[(size_t)g * FOUT + colBase] = pk;
        }
    }

    // fused s epilogue (fp32 accumulators)
    float4 asv = *(const float4*)&a_src[colBase];
    float4 adv = *(const float4*)&a_dst[colBase];

    __syncthreads();
    float* ps = sm;                // 128*17
    float* pd = sm + 128 * 17;     // 128*17
#pragma unroll
    for (int i = 0; i < 8; i++) {
        int row = rowBase + i;
        float vs = acc[i][0] * asv.x + acc[i][1] * asv.y +
                   acc[i][2] * asv.z + acc[i][3] * asv.w;
        float vd = acc[i][0] * adv.x + acc[i][1] * adv.y +
                   acc[i][2] * adv.z + acc[i][3] * adv.w;
        ps[row * 17 + t16] = vs;
        pd[row * 17 + t16] = vd;
    }
    __syncthreads();
    if (tid < 128) {
        float s1 = 0.f, s2 = 0.f;
#pragma unroll
        for (int k = 0; k < 16; k++) {
            s1 += ps[tid * 17 + k];
            s2 += pd[tid * 17 + k];
        }
        int g = r0 + tid;
        if (g < N) { ssrc[g] = s1; sdst[g] = s2; }
    }
}

// ---------------- 3) fill: e = exp(leaky(l)) unshifted; bucket by dst -------
// Max-shift dropped: alpha = e/(sum e + 1e-16) is invariant to the shift to
// ~1e-13 relative (denominators >> 1e-16 at the true-max shift; logits bounded
// ~±10 so exp never overflows).
__global__ void fill_kernel(const void* __restrict__ ei,
                            const float* __restrict__ ssrc,
                            const float* __restrict__ sdst,
                            const int* __restrict__ rowstart,
                            int* __restrict__ cursor,
                            uint2* __restrict__ bkt, int E, int N) {
    int is64 = detect_is64((const unsigned*)ei);
    int i = blockIdx.x * blockDim.x + threadIdx.x;
    if (i >= E) return;
    int s, d;
    load_edge(ei, is64, E, i, N, s, d);
    float t = ssrc[s] + sdst[d];
    float l = t > 0.f ? t : NEG * t;
    float e = __expf(l);
    int pos = atomicAdd(&cursor[d], 1);
    bkt[rowstart[d] + pos] = make_uint2((unsigned)s, __float_as_uint(e));
}

// ---------------- 4) gather + state cleanup ---------------------------------
// 8 threads/node; lane owns 8 cols (16B of halves); 2-way unroll; fp32 accum.
// Epilogue zeroes deg/cursor for the NEXT invocation (graph-replay safe).
__global__ void gather_kernel(const uint2* __restrict__ bkt,
                              const int* __restrict__ rowstart,
                              int* __restrict__ deg,
                              int* __restrict__ cursor,
                              const __half* __restrict__ Whh,
                              float* __restrict__ out, int N) {
    int t = blockIdx.x * blockDim.x + threadIdx.x;
    int node = t >> 3;
    int l = t & 7;
    if (node >= N) return;
    int beg = rowstart[node];
    int dg  = deg[node];
    int end = beg + dg;

    float a0[8], a1[8];
#pragma unroll
    for (int k = 0; k < 8; k++) { a0[k] = 0.f; a1[k] = 0.f; }
    float den0 = 0.f, den1 = 0.f;

    int j = beg;
    for (; j + 2 <= end; j += 2) {
        uint2 b0 = __ldg(&bkt[j]);
        uint2 b1 = __ldg(&bkt[j + 1]);
        uint4 v0 = *(const uint4*)&Whh[(size_t)b0.x * FOUT + l * 8];
        uint4 v1 = *(const uint4*)&Whh[(size_t)b1.x * FOUT + l * 8];
        float e0 = __uint_as_float(b0.y);
        float e1 = __uint_as_float(b1.y);
        den0 += e0;
        den1 += e1;
        {
            float2 f0 = __half22float2(*(__half2*)&v0.x);
            float2 f1 = __half22float2(*(__half2*)&v0.y);
            float2 f2 = __half22float2(*(__half2*)&v0.z);
            float2 f3 = __half22float2(*(__half2*)&v0.w);
            a0[0] = fmaf(e0, f0.x, a0[0]); a0[1] = fmaf(e0, f0.y, a0[1]);
            a0[2] = fmaf(e0, f1.x, a0[2]); a0[3] = fmaf(e0, f1.y, a0[3]);
            a0[4] = fmaf(e0, f2.x, a0[4]); a0[5] = fmaf(e0, f2.y, a0[5]);
            a0[6] = fmaf(e0, f3.x, a0[6]); a0[7] = fmaf(e0, f3.y, a0[7]);
        }
        {
            float2 f0 = __half22float2(*(__half2*)&v1.x);
            float2 f1 = __half22float2(*(__half2*)&v1.y);
            float2 f2 = __half22float2(*(__half2*)&v1.z);
            float2 f3 = __half22float2(*(__half2*)&v1.w);
            a1[0] = fmaf(e1, f0.x, a1[0]); a1[1] = fmaf(e1, f0.y, a1[1]);
            a1[2] = fmaf(e1, f1.x, a1[2]); a1[3] = fmaf(e1, f1.y, a1[3]);
            a1[4] = fmaf(e1, f2.x, a1[4]); a1[5] = fmaf(e1, f2.y, a1[5]);
            a1[6] = fmaf(e1, f3.x, a1[6]); a1[7] = fmaf(e1, f3.y, a1[7]);
        }
    }
    if (j < end) {
        uint2 b0 = __ldg(&bkt[j]);
        uint4 v0 = *(const uint4*)&Whh[(size_t)b0.x * FOUT + l * 8];
        float e0 = __uint_as_float(b0.y);
        den0 += e0;
        float2 f0 = __half22float2(*(__half2*)&v0.x);
        float2 f1 = __half22float2(*(__half2*)&v0.y);
        float2 f2 = __half22float2(*(__half2*)&v0.z);
        float2 f3 = __half22float2(*(__half2*)&v0.w);
        a0[0] = fmaf(e0, f0.x, a0[0]); a0[1] = fmaf(e0, f0.y, a0[1]);
        a0[2] = fmaf(e0, f1.x, a0[2]); a0[3] = fmaf(e0, f1.y, a0[3]);
        a0[4] = fmaf(e0, f2.x, a0[4]); a0[5] = fmaf(e0, f2.y, a0[5]);
        a0[6] = fmaf(e0, f3.x, a0[6]); a0[7] = fmaf(e0, f3.y, a0[7]);
    }

    float denom = den0 + den1;
    float inv = __fdividef(1.f, denom + 1e-16f);

    float r[8];
#pragma unroll
    for (int k = 0; k < 8; k++) {
        float v = (a0[k] + a1[k]) * inv;
        r[k] = v > 0.f ? v : expm1f(v);
    }
    *(float4*)&out[(size_t)node * FOUT + l * 8] =
        make_float4(r[0], r[1], r[2], r[3]);
    *(float4*)&out[(size_t)node * FOUT + l * 8 + 4] =
        make_float4(r[4], r[5], r[6], r[7]);

    // cleanup for next invocation (deg/cursor consumed above / in fill)
    if (l == 0) deg[node] = 0;
    if (l == 1) cursor[node] = 0;
}

// ---------------- launch ----------------------------------------------------
extern "C" void kernel_launch(void* const* d_in, const int* in_sizes, int n_in,
                              void* d_out, int out_size) {
    const float* x = 0;
    const void*  ei = 0;
    const float* W = 0;
    const float* a_src = 0;
    const float* a_dst = 0;
    int x_sz = 0, ei_sz = 0;

    for (int i = 0; i < n_in; i++) {
        int sz = in_sizes[i];
        if (sz == 64) {
            if (!a_src) a_src = (const float*)d_in[i];
            else        a_dst = (const float*)d_in[i];
        } else if (sz == FIN * FOUT) {
            W = (const float*)d_in[i];
        } else if (sz > x_sz) {
            ei = (const void*)x; ei_sz = x_sz;
            x = (const float*)d_in[i]; x_sz = sz;
        } else {
            ei = (const void*)d_in[i]; ei_sz = sz;
        }
    }

    float* out = (float*)d_out;
    int N = x_sz / FIN;
    int E = ei_sz / 2;

    void *pWhh, *pss, *psd, *pdeg, *pcur, *prow, *pbkt, *ptot;
    cudaGetSymbolAddress(&pWhh, g_Whh);
    cudaGetSymbolAddress(&pss, g_ssrc);
    cudaGetSymbolAddress(&psd, g_sdst);
    cudaGetSymbolAddress(&pdeg, g_deg);
    cudaGetSymbolAddress(&pcur, g_cursor);
    cudaGetSymbolAddress(&prow, g_rowstart);
    cudaGetSymbolAddress(&pbkt, g_bkt);
    cudaGetSymbolAddress(&ptot, g_total);

    count_kernel<<<1184, 256>>>(ei, (int*)pdeg, (int*)ptot, E, N);

    int gemmBlocks = (N + 127) / 128;
    int allocBlocks = (N + 255) / 256;
    cudaFuncSetAttribute(gemm_kernel,
                         cudaFuncAttributeMaxDynamicSharedMemorySize, 96 * 1024);
    gemm_kernel<<<gemmBlocks + allocBlocks, 256, 96 * 1024>>>(
        x, W, a_src, a_dst, (__half*)pWhh, (float*)pss, (float*)psd,
        (int*)pdeg, (int*)prow, (int*)ptot, gemmBlocks, N);

    fill_kernel<<<(E + 255) / 256, 256>>>(ei, (float*)pss, (float*)psd,
                                          (int*)prow, (int*)pcur,
                                          (uint2*)pbkt, E, N);

    long long gthreads = (long long)N * 8;
    gather_kernel<<<(int)((gthreads + 255) / 256), 256>>>(
        (uint2*)pbkt, (int*)prow, (int*)pdeg, (int*)pcur,
        (const __half*)pWhh, out, N);
}